// round 13
// baseline (speedup 1.0000x reference)
#include <cuda_runtime.h>

// logLikelihood_loss: sum over (B,T,P) of -log(clip(bivariate_gaussian_pdf, 1e-10)) / P
// B=64, T=128, P=512 -> 4,194,304 elements. y_target: (...,3) f32, o_pred: (...,5) f32.
// HBM-bound streaming reduction. Log-domain formulation avoids exp/log round-trip.
//
// R12: R10's single packed-u64 tail left a 5-DRAM-point gap vs the clean R1
//      compute (4096 relaxed RMWs on ONE address -> serialized LTS atomic ALU
//      hotspot + blocks holding SM slots in the retire queue; occ 92.7->85.5).
//      Spread it: two-level packed-atomic tree. L1 = 32 slot words on distinct
//      128B lines (block b -> slot b&31, ~128 ops/word, 32x less per-address
//      serialization); each slot winner forwards its packed total to one root
//      word (32 ops). Same {count:12 | biased Q32 sum:52} trick at both levels:
//      per-location atomicity supplies all ordering -- still no fence, no
//      acquire, no L1 invalidate. Winners atomicExch their word to 0 ->
//      deterministic and graph-replay-safe. Compute section identical to R1.

#define N_ELEM   4194304
#define GROUPS   (N_ELEM / 4)        // 4 records per thread
#define THREADS  256
#define BLOCKS   (GROUPS / THREADS)  // 4096

#define NSLOTS      32
#define SLOT_STRIDE 16               // 16 u64 = 128B -> one slot per L2 line
#define PER_SLOT    (BLOCKS / NSLOTS)  // 128 contributions per slot

// Fixed-point packing: bits [0:52) = biased Q32 sum, bits [52:64) = count.
// Per-block v = block_sum/512, |v| <= ~46; BIAS keeps the field positive.
// L1 slot range: 128*(46+64)*2^32 < 2^46. Root: 32 slot totals < 2^51. OK.
#define PACK_BIAS   64.0
#define PACK_SCALE  4294967296.0     // 2^32
#define SUM_MASK    ((1ULL << 52) - 1)

__device__ unsigned long long g_slot[NSLOTS * SLOT_STRIDE];  // zero-init, self-resetting
__device__ unsigned long long g_root = 0ULL;                 // self-resetting

// Accurate tanh from fast exp (independent of -use_fast_math's tanh.approx,
// whose abs error would poison 1-rho^2).
__device__ __forceinline__ float fast_tanh(float x) {
    float ax = fabsf(x);
    float e  = __expf(2.0f * ax);
    float t  = 1.0f - __fdividef(2.0f, e + 1.0f);
    return copysignf(t, x);
}

__global__ __launch_bounds__(THREADS)
void nll_kernel(const float* __restrict__ y, const float* __restrict__ o,
                float* __restrict__ out) {
    const int g = blockIdx.x * blockDim.x + threadIdx.x;   // group of 4 records

    // Direct AoS loads: 5 float4 from o_pred, 3 float4 from y_target.
    // All 8 LDG.128 issue up front -> full-chip burst keeps DRAM saturated.
    const float4* o4 = reinterpret_cast<const float4*>(o) + (size_t)g * 5;
    const float4* y4 = reinterpret_cast<const float4*>(y) + (size_t)g * 3;

    float of[20], yf[12];
#pragma unroll
    for (int k = 0; k < 5; k++) reinterpret_cast<float4*>(of)[k] = o4[k];
#pragma unroll
    for (int k = 0; k < 3; k++) reinterpret_cast<float4*>(yf)[k] = y4[k];

    const float LOG_2PI  = 1.8378770664093453f;   // ln(2*pi)
    const float CLAMP_HI = 23.025850929940457f;   // -ln(1e-10)

    float acc = 0.0f;
#pragma unroll
    for (int j = 0; j < 4; j++) {
        float mux = of[5 * j + 0];
        float muy = of[5 * j + 1];
        float lsx = of[5 * j + 2];   // log(sx)
        float lsy = of[5 * j + 3];   // log(sy)
        float cra = of[5 * j + 4];   // pre-tanh corr

        float y1 = yf[3 * j + 1];
        float y2 = yf[3 * j + 2];

        float inv_sx = __expf(-lsx);
        float inv_sy = __expf(-lsy);
        float nx = (y1 - mux) * inv_sx;
        float ny = (y2 - muy) * inv_sy;

        float tt = fast_tanh(cra);
        float om = fmaf(-tt, tt, 1.0f);            // 1 - rho^2 > 0
        float z  = fmaf(nx, nx, fmaf(ny, ny, -2.0f * tt * nx * ny));

        // -log pdf = z/(2*om) + log(2pi) + log(sx) + log(sy) + 0.5*log(om)
        float nll = 0.5f * __fdividef(z, om)
                  + (LOG_2PI + lsx + lsy + 0.5f * __logf(om));
        acc += fminf(nll, CLAMP_HI);               // == -log(clip(pdf, 1e-10))
    }

    // ── Block reduction (identical to R1) ─────────────────────────────────
#pragma unroll
    for (int off = 16; off; off >>= 1)
        acc += __shfl_down_sync(0xffffffffu, acc, off);

    __shared__ float wsum[THREADS / 32];
    const int lane = threadIdx.x & 31;
    const int wid  = threadIdx.x >> 5;
    if (lane == 0) wsum[wid] = acc;
    __syncthreads();

    if (wid == 0) {
        float v = (lane < THREADS / 32) ? wsum[lane] : 0.0f;
#pragma unroll
        for (int off = 4; off; off >>= 1)
            v += __shfl_down_sync(0xffffffffu, v, off);

        if (lane == 0) {
            // ── Level 1: packed relaxed RMW into this block's slot word ──
            double vb = (double)(v * (1.0f / 512.0f)) + PACK_BIAS;
            unsigned long long pack =
                (1ULL << 52) | (unsigned long long)llrint(vb * PACK_SCALE);
            unsigned long long* slot = &g_slot[(blockIdx.x & (NSLOTS - 1)) * SLOT_STRIDE];
            unsigned long long old = atomicAdd(slot, pack);   // relaxed RMW

            if ((old >> 52) == (unsigned long long)(PER_SLOT - 1)) {
                // Slot winner: owns the slot total (same-word atomicity).
                unsigned long long slot_total = (old + pack) & SUM_MASK; // Q32, incl. 128 biases
                atomicExch(slot, 0ULL);                       // reset for next replay

                // ── Level 2: forward packed slot total to the root word ──
                unsigned long long rpack = (1ULL << 52) | slot_total;
                unsigned long long rold = atomicAdd(&g_root, rpack);

                if ((rold >> 52) == (unsigned long long)(NSLOTS - 1)) {
                    unsigned long long total = (rold + rpack) & SUM_MASK;
                    double s = (double)total * (1.0 / PACK_SCALE)
                             - PACK_BIAS * (double)BLOCKS;
                    out[0] = (float)s;
                    atomicExch(&g_root, 0ULL);                // reset for next replay
                }
            }
        }
    }
}

extern "C" void kernel_launch(void* const* d_in, const int* in_sizes, int n_in,
                              void* d_out, int out_size) {
    const float* y = (const float*)d_in[0];   // y_target, 12,582,912 floats
    const float* o = (const float*)d_in[1];   // o_pred,  20,971,520 floats
    float* out = (float*)d_out;               // scalar fp32

    nll_kernel<<<BLOCKS, THREADS>>>(y, o, out);
}

// round 14
// speedup vs baseline: 1.0266x; 1.0266x over previous
#include <cuda_runtime.h>

// logLikelihood_loss: sum over (B,T,P) of -log(clip(bivariate_gaussian_pdf, 1e-10)) / P
// B=64, T=128, P=512 -> 4,194,304 elements. y_target: (...,3) f32, o_pred: (...,5) f32.
// HBM-bound streaming reduction. Log-domain formulation avoids exp/log round-trip.
//
// R13: R12 disproved the atomic-throughput theory (spreading addresses made it
//      worse). Real cost: every block's lane-0 WAITED on the ATOMG return
//      (~318+cyc + retire-burst queueing) before block exit, stalling wave
//      turnover (occ 92.7 -> ~85). Fix: workers issue a fire-and-forget
//      red.relaxed.gpu.add.u64 of the packed word and exit immediately (REDG
//      has no return trip). One thread of block 0 (first wave) spins on the
//      word with atom.add-0 (L2-coherent RMW; plain loads could spin on a
//      stale L1 line) + __nanosleep, then unpacks, writes out[0], and
//      atomicExch-resets -> deterministic, graph-replay-safe, zero fences.
//      Packing: sum bits [0:51) (range 2^50.8, fits), count bits [51:64)
//      (13 bits -> 4096 arrivals representable without wrap).

#define N_ELEM   4194304
#define GROUPS   (N_ELEM / 4)        // 4 records per thread
#define THREADS  256
#define BLOCKS   (GROUPS / THREADS)  // 4096

// Fixed-point packing: bits [0:51) = (v + BIAS)*2^32 summed, bits [51:64) = count.
// Per-block v = block_sum/512 in [-12, 46.1]; BIAS=64 keeps the field positive.
// Max total: 4096 * (64+46.1) * 2^32 = 2^50.8 < 2^51. Count: 4096 < 2^13.
#define PACK_BIAS   64.0
#define PACK_SCALE  4294967296.0     // 2^32
#define CNT_SHIFT   51
#define SUM_MASK    ((1ULL << CNT_SHIFT) - 1)

__device__ unsigned long long g_pack = 0ULL;   // reset by spinner each run

// Accurate tanh from fast exp (independent of -use_fast_math's tanh.approx,
// whose abs error would poison 1-rho^2).
__device__ __forceinline__ float fast_tanh(float x) {
    float ax = fabsf(x);
    float e  = __expf(2.0f * ax);
    float t  = 1.0f - __fdividef(2.0f, e + 1.0f);
    return copysignf(t, x);
}

__global__ __launch_bounds__(THREADS)
void nll_kernel(const float* __restrict__ y, const float* __restrict__ o,
                float* __restrict__ out) {
    const int g = blockIdx.x * blockDim.x + threadIdx.x;   // group of 4 records

    // Direct AoS loads: 5 float4 from o_pred, 3 float4 from y_target.
    // All 8 LDG.128 issue up front -> full-chip burst keeps DRAM saturated.
    const float4* o4 = reinterpret_cast<const float4*>(o) + (size_t)g * 5;
    const float4* y4 = reinterpret_cast<const float4*>(y) + (size_t)g * 3;

    float of[20], yf[12];
#pragma unroll
    for (int k = 0; k < 5; k++) reinterpret_cast<float4*>(of)[k] = o4[k];
#pragma unroll
    for (int k = 0; k < 3; k++) reinterpret_cast<float4*>(yf)[k] = y4[k];

    const float LOG_2PI  = 1.8378770664093453f;   // ln(2*pi)
    const float CLAMP_HI = 23.025850929940457f;   // -ln(1e-10)

    float acc = 0.0f;
#pragma unroll
    for (int j = 0; j < 4; j++) {
        float mux = of[5 * j + 0];
        float muy = of[5 * j + 1];
        float lsx = of[5 * j + 2];   // log(sx)
        float lsy = of[5 * j + 3];   // log(sy)
        float cra = of[5 * j + 4];   // pre-tanh corr

        float y1 = yf[3 * j + 1];
        float y2 = yf[3 * j + 2];

        float inv_sx = __expf(-lsx);
        float inv_sy = __expf(-lsy);
        float nx = (y1 - mux) * inv_sx;
        float ny = (y2 - muy) * inv_sy;

        float tt = fast_tanh(cra);
        float om = fmaf(-tt, tt, 1.0f);            // 1 - rho^2 > 0
        float z  = fmaf(nx, nx, fmaf(ny, ny, -2.0f * tt * nx * ny));

        // -log pdf = z/(2*om) + log(2pi) + log(sx) + log(sy) + 0.5*log(om)
        float nll = 0.5f * __fdividef(z, om)
                  + (LOG_2PI + lsx + lsy + 0.5f * __logf(om));
        acc += fminf(nll, CLAMP_HI);               // == -log(clip(pdf, 1e-10))
    }

    // ── Block reduction (identical to R1) ─────────────────────────────────
#pragma unroll
    for (int off = 16; off; off >>= 1)
        acc += __shfl_down_sync(0xffffffffu, acc, off);

    __shared__ float wsum[THREADS / 32];
    const int lane = threadIdx.x & 31;
    const int wid  = threadIdx.x >> 5;
    if (lane == 0) wsum[wid] = acc;
    __syncthreads();

    if (wid == 0) {
        float v = (lane < THREADS / 32) ? wsum[lane] : 0.0f;
#pragma unroll
        for (int off = 4; off; off >>= 1)
            v += __shfl_down_sync(0xffffffffu, v, off);

        if (lane == 0) {
            // Fire-and-forget RED of the packed contribution: no return trip,
            // block exits immediately -> wave turnover never stalls.
            double vb = (double)(v * (1.0f / 512.0f)) + PACK_BIAS;
            unsigned long long pack =
                (1ULL << CNT_SHIFT) | (unsigned long long)llrint(vb * PACK_SCALE);
            asm volatile("red.relaxed.gpu.global.add.u64 [%0], %1;"
                         :: "l"(&g_pack), "l"(pack) : "memory");

            // ── Spinner: one thread of block 0 finalizes ─────────────────
            if (blockIdx.x == 0) {
                unsigned long long cur;
                do {
                    __nanosleep(256);
                    asm volatile("atom.relaxed.gpu.global.add.u64 %0, [%1], %2;"
                                 : "=l"(cur) : "l"(&g_pack), "l"(0ULL) : "memory");
                } while ((cur >> CNT_SHIFT) != (unsigned long long)BLOCKS);

                double s = (double)(cur & SUM_MASK) * (1.0 / PACK_SCALE)
                         - PACK_BIAS * (double)BLOCKS;
                out[0] = (float)s;
                atomicExch(&g_pack, 0ULL);   // reset for next graph replay
            }
        }
    }
}

extern "C" void kernel_launch(void* const* d_in, const int* in_sizes, int n_in,
                              void* d_out, int out_size) {
    const float* y = (const float*)d_in[0];   // y_target, 12,582,912 floats
    const float* o = (const float*)d_in[1];   // o_pred,  20,971,520 floats
    float* out = (float*)d_out;               // scalar fp32

    nll_kernel<<<BLOCKS, THREADS>>>(y, o, out);
}